// round 8
// baseline (speedup 1.0000x reference)
#include <cuda_runtime.h>

// OSTL one-step forward, single fused kernel:
//   I      = x @ W;  u_new = sig_tau*u + I;  s = (u_new-1 > 0);
//   u_out  = u_new - s;  J_new = sig_tau*J + x[:,None]
// Outputs in d_out: [u_out (8192) | J_new (8192*8192) | s (8192)]
//
// Reduction: each (col-group, row-block) block writes a partial; the last
// arrival per column group (atomic counter) reduces all 128 partials with an
// 8-warp split + fixed-order smem tree -> deterministic. Counter reset by the
// finalizer -> graph-replay idempotent.

static constexpr int   IN_SZ  = 8192;
static constexpr int   OUT_SZ = 8192;
static constexpr float SIG_TAU = 0.8807970779778823f;  // sigmoid(2.0)

static constexpr int ROWS_PER_BLK = 64;
static constexpr int ROW_BLKS     = IN_SZ / ROWS_PER_BLK;   // 128
static constexpr int COL_BLKS     = OUT_SZ / (256 * 4);     // 8
static constexpr int KG           = 8;                      // tail k-groups (warps)
static constexpr int K_PER        = ROW_BLKS / KG;          // 16

__device__ float g_partial[ROW_BLKS * OUT_SZ];   // 4 MiB partials
__device__ int   g_count[COL_BLKS];              // zero-init; reset by finalizer

__global__ void __launch_bounds__(256, 4)
fused_ostl(const float* __restrict__ x,
           const float* __restrict__ u,
           const float* __restrict__ J,
           const float* __restrict__ W,
           float*       __restrict__ Jout,
           float*       __restrict__ u_out,
           float*       __restrict__ s_out)
{
    __shared__ float  xs[ROWS_PER_BLK];
    __shared__ int    is_last;
    __shared__ float4 red[KG][256];   // 32 KiB tail scratch

    const int t    = threadIdx.x;
    const int row0 = blockIdx.y * ROWS_PER_BLK;
    if (t < ROWS_PER_BLK) xs[t] = x[row0 + t];
    __syncthreads();

    const int col4 = blockIdx.x * 256 + t;            // float4 column index
    const float4* __restrict__ J4 = (const float4*)J;
    const float4* __restrict__ W4 = (const float4*)W;
    float4*       __restrict__ O4 = (float4*)Jout;

    float a0 = 0.f, a1 = 0.f, a2 = 0.f, a3 = 0.f;

    #pragma unroll 8
    for (int r = 0; r < ROWS_PER_BLK; ++r) {
        const size_t idx = (size_t)(row0 + r) * (OUT_SZ / 4) + col4;
        const float xi = xs[r];
        const float4 w = W4[idx];
        const float4 j = J4[idx];
        float4 jn;
        jn.x = fmaf(SIG_TAU, j.x, xi);
        jn.y = fmaf(SIG_TAU, j.y, xi);
        jn.z = fmaf(SIG_TAU, j.z, xi);
        jn.w = fmaf(SIG_TAU, j.w, xi);
        O4[idx] = jn;
        a0 = fmaf(xi, w.x, a0);
        a1 = fmaf(xi, w.y, a1);
        a2 = fmaf(xi, w.z, a2);
        a3 = fmaf(xi, w.w, a3);
    }

    float4* P4 = (float4*)g_partial;
    P4[(size_t)blockIdx.y * (OUT_SZ / 4) + col4] = make_float4(a0, a1, a2, a3);

    __threadfence();
    if (t == 0) {
        int old = atomicAdd(&g_count[blockIdx.x], 1);
        is_last = (old == ROW_BLKS - 1);
    }
    __syncthreads();

    if (!is_last) return;

    // ---- Tail: warp-split reduction over 128 partials (fixed order) ----
    const int lane = t & 31;
    const int kg   = t >> 5;                 // warp id = k-group
    const int cb   = blockIdx.x * 256;       // first float4 col of this group

    #pragma unroll
    for (int i = 0; i < 8; ++i) {            // 8 x 32 lanes = 256 col4
        const int c = lane + 32 * i;
        float4 s4 = make_float4(0.f, 0.f, 0.f, 0.f);
        #pragma unroll
        for (int k = kg * K_PER; k < kg * K_PER + K_PER; ++k) {
            const float4 p = P4[(size_t)k * (OUT_SZ / 4) + cb + c];
            s4.x += p.x; s4.y += p.y; s4.z += p.z; s4.w += p.w;
        }
        red[kg][c] = s4;
    }
    __syncthreads();

    {
        float4 tot = make_float4(0.f, 0.f, 0.f, 0.f);
        #pragma unroll
        for (int g = 0; g < KG; ++g) {
            const float4 p = red[g][t];
            tot.x += p.x; tot.y += p.y; tot.z += p.z; tot.w += p.w;
        }
        const int  oc = cb + t;
        const float4 uv = ((const float4*)u)[oc];
        tot.x = fmaf(SIG_TAU, uv.x, tot.x);
        tot.y = fmaf(SIG_TAU, uv.y, tot.y);
        tot.z = fmaf(SIG_TAU, uv.z, tot.z);
        tot.w = fmaf(SIG_TAU, uv.w, tot.w);

        float4 sp;
        sp.x = (tot.x - 1.0f) > 0.0f ? 1.0f : 0.0f;
        sp.y = (tot.y - 1.0f) > 0.0f ? 1.0f : 0.0f;
        sp.z = (tot.z - 1.0f) > 0.0f ? 1.0f : 0.0f;
        sp.w = (tot.w - 1.0f) > 0.0f ? 1.0f : 0.0f;

        float4 uo;
        uo.x = tot.x - sp.x;   // (V_TH - V_RESET) = 1.0
        uo.y = tot.y - sp.y;
        uo.z = tot.z - sp.z;
        uo.w = tot.w - sp.w;

        ((float4*)s_out)[oc] = sp;
        ((float4*)u_out)[oc] = uo;
    }

    if (t == 0) g_count[blockIdx.x] = 0;   // replay-idempotent
}

extern "C" void kernel_launch(void* const* d_in, const int* in_sizes, int n_in,
                              void* d_out, int out_size)
{
    const float* x = (const float*)d_in[0];
    const float* u = (const float*)d_in[1];
    const float* J = (const float*)d_in[2];
    const float* W = (const float*)d_in[3];

    float* out   = (float*)d_out;
    float* u_out = out;
    float* Jout  = out + OUT_SZ;
    float* s_out = out + OUT_SZ + (size_t)IN_SZ * OUT_SZ;

    fused_ostl<<<dim3(COL_BLKS, ROW_BLKS), 256>>>(x, u, J, W, Jout, u_out, s_out);
}

// round 9
// speedup vs baseline: 1.0903x; 1.0903x over previous
#include <cuda_runtime.h>

// OSTL one-step forward (two kernels, PDL-overlapped):
//   I      = x @ W                      (column sums over rows of W)
//   u_new  = sig_tau*u + I
//   s      = (u_new - 1 > 0) ? 1 : 0
//   u_out  = u_new - s                  (V_TH - V_RESET = 1.0)
//   J_new  = sig_tau*J + x[:,None]
//
// Outputs concatenated in d_out: [u_out (8192) | J_new (8192*8192) | s (8192)]
//
// finalize is launched with programmatic stream serialization: its launch and
// independent loads (u) overlap the main kernel's tail; partials are consumed
// only after cudaGridDependencySynchronize() -> correct and deterministic.

static constexpr int   IN_SZ  = 8192;
static constexpr int   OUT_SZ = 8192;
static constexpr float SIG_TAU = 0.8807970779778823f;  // sigmoid(2.0)

static constexpr int ROWS_PER_BLK = 64;
static constexpr int ROW_BLKS     = IN_SZ / ROWS_PER_BLK;   // 128
static constexpr int COL_BLKS     = OUT_SZ / (256 * 4);     // 8 (256 thr * float4)

// Deterministic matvec partials: one slot per (row-block, column). 4 MiB.
__device__ float g_partial[ROW_BLKS * OUT_SZ];

__global__ void __launch_bounds__(256, 4)
fused_trace_matvec(const float* __restrict__ x,
                   const float* __restrict__ J,
                   const float* __restrict__ W,
                   float*       __restrict__ Jout)
{
    __shared__ float xs[ROWS_PER_BLK];
    const int t    = threadIdx.x;
    const int row0 = blockIdx.y * ROWS_PER_BLK;
    if (t < ROWS_PER_BLK) xs[t] = x[row0 + t];
    __syncthreads();

    const int col4 = blockIdx.x * 256 + t;            // float4 column index (0..2047)
    const float4* __restrict__ J4 = (const float4*)J;
    const float4* __restrict__ W4 = (const float4*)W;
    float4*       __restrict__ O4 = (float4*)Jout;

    float a0 = 0.f, a1 = 0.f, a2 = 0.f, a3 = 0.f;

    #pragma unroll 8
    for (int r = 0; r < ROWS_PER_BLK; ++r) {
        const size_t idx = (size_t)(row0 + r) * (OUT_SZ / 4) + col4;
        const float xi = xs[r];
        const float4 w = W4[idx];
        const float4 j = J4[idx];
        float4 jn;
        jn.x = fmaf(SIG_TAU, j.x, xi);
        jn.y = fmaf(SIG_TAU, j.y, xi);
        jn.z = fmaf(SIG_TAU, j.z, xi);
        jn.w = fmaf(SIG_TAU, j.w, xi);
        O4[idx] = jn;
        a0 = fmaf(xi, w.x, a0);
        a1 = fmaf(xi, w.y, a1);
        a2 = fmaf(xi, w.z, a2);
        a3 = fmaf(xi, w.w, a3);
    }

    float4* P4 = (float4*)(g_partial + (size_t)blockIdx.y * OUT_SZ);
    P4[col4] = make_float4(a0, a1, a2, a3);

    // Allow the dependent finalize kernel to begin launching.
    cudaTriggerProgrammaticLaunchCompletion();
}

// Finalize (R2 v1 + PDL): 256 blocks x 256 threads. Each block owns 32
// columns. 8 warps split the 128 k-partials (16 each), fixed-order smem tree.
static constexpr int FIN_COLS   = 32;                  // columns per block
static constexpr int FIN_KGRPS  = 8;                   // warps per block
static constexpr int K_PER_GRP  = ROW_BLKS / FIN_KGRPS; // 16

__global__ void __launch_bounds__(256)
finalize(const float* __restrict__ u,
         float* __restrict__ u_out,
         float* __restrict__ s_out)
{
    __shared__ float sdata[FIN_KGRPS][FIN_COLS];

    const int c    = threadIdx.x & 31;        // column within block's group
    const int kg   = threadIdx.x >> 5;        // warp id = k-group
    const int col  = blockIdx.x * FIN_COLS + c;

    // u does not depend on the primary kernel: prepay its DRAM latency
    // before waiting for the primary grid.
    const float uval = u[col];

    cudaGridDependencySynchronize();

    float sum = 0.f;
    #pragma unroll
    for (int i = 0; i < K_PER_GRP; ++i) {
        const int k = kg * K_PER_GRP + i;
        sum += g_partial[(size_t)k * OUT_SZ + col];
    }
    sdata[kg][c] = sum;
    __syncthreads();

    if (kg == 0) {
        float tot = SIG_TAU * uval;
        #pragma unroll
        for (int g = 0; g < FIN_KGRPS; ++g)
            tot += sdata[g][c];
        const float sp = (tot - 1.0f) > 0.0f ? 1.0f : 0.0f;
        s_out[col] = sp;
        u_out[col] = tot - sp;   // (V_TH - V_RESET) = 1.0
    }
}

extern "C" void kernel_launch(void* const* d_in, const int* in_sizes, int n_in,
                              void* d_out, int out_size)
{
    const float* x = (const float*)d_in[0];
    const float* u = (const float*)d_in[1];
    const float* J = (const float*)d_in[2];
    const float* W = (const float*)d_in[3];

    float* out   = (float*)d_out;
    float* u_out = out;
    float* Jout  = out + OUT_SZ;
    float* s_out = out + OUT_SZ + (size_t)IN_SZ * OUT_SZ;

    fused_trace_matvec<<<dim3(COL_BLKS, ROW_BLKS), 256>>>(x, J, W, Jout);

    // Dependent launch: overlap finalize's launch/ramp with the primary tail.
    cudaLaunchConfig_t cfg = {};
    cfg.gridDim  = dim3(OUT_SZ / FIN_COLS);
    cfg.blockDim = dim3(256);
    cfg.dynamicSmemBytes = 0;
    cfg.stream = 0;  // legacy default stream (same as <<<>>> above)
    cudaLaunchAttribute attr[1];
    attr[0].id = cudaLaunchAttributeProgrammaticStreamSerialization;
    attr[0].val.programmaticStreamSerializationAllowed = 1;
    cfg.attrs = attr;
    cfg.numAttrs = 1;
    cudaLaunchKernelEx(&cfg, finalize, u, u_out, s_out);
}